// round 11
// baseline (speedup 1.0000x reference)
#include <cuda_runtime.h>
#include <cuda_bf16.h>
#include <math.h>

#define B_ 4
#define L_ 1024
#define H_ 16
#define DK 64

// Scratch (device globals; no allocation allowed)
__device__ __align__(16) unsigned g_xh[4096*512], g_xl[4096*512];       // x packed bf16x2 (k-pairs)
__device__ __align__(16) unsigned g_wh[4*1024*512], g_wl[4*1024*512];   // Wq,Wk,Wv,Wo packed
__device__ __align__(16) unsigned g_qh[B_*H_*L_*32], g_ql[B_*H_*L_*32]; // Q packed (dk-pairs)
__device__ __align__(16) unsigned g_kh[B_*H_*L_*32], g_kl[B_*H_*L_*32];
__device__ __align__(16) float    g_v [B_*H_*L_*DK];
__device__ __align__(16) unsigned g_ctxh[B_*H_*L_*32], g_ctxl[B_*H_*L_*32];
__device__ float g_bias[B_*L_*L_];
__device__ float g_proj[B_*L_*H_];

__device__ __forceinline__ int clampi(int v, int lo, int hi){
    return v < lo ? lo : (v > hi ? hi : v);
}

// Split an fp32 pair into packed bf16x2 hi and lo words (x -> low half).
__device__ __forceinline__ void split2(float x, float y, unsigned& hiw, unsigned& low){
    __nv_bfloat16 hx = __float2bfloat16(x);
    __nv_bfloat16 hy = __float2bfloat16(y);
    float rx = x - __bfloat162float(hx);
    float ry = y - __bfloat162float(hy);
    __nv_bfloat162 h; h.x = hx; h.y = hy;
    __nv_bfloat162 l = __floats2bfloat162_rn(rx, ry);
    hiw = *(unsigned*)&h;
    low = *(unsigned*)&l;
}

// m16n8k16 bf16 mma, f32 accumulate
__device__ __forceinline__ void mma_bf16(float* c, const unsigned* a, const unsigned* b){
    asm volatile(
        "mma.sync.aligned.m16n8k16.row.col.f32.bf16.bf16.f32 "
        "{%0,%1,%2,%3},{%4,%5,%6,%7},{%8,%9},{%0,%1,%2,%3};"
        : "+f"(c[0]), "+f"(c[1]), "+f"(c[2]), "+f"(c[3])
        : "r"(a[0]), "r"(a[1]), "r"(a[2]), "r"(a[3]), "r"(b[0]), "r"(b[1]));
}

// Convert fp32 array -> packed bf16x2 hi/lo (pairs along fastest dim)
__global__ void prep_convert(const float* __restrict__ src, unsigned* __restrict__ dh,
                             unsigned* __restrict__ dl, int n4){
    int i = blockIdx.x * 256 + threadIdx.x;
    if (i >= n4) return;
    float4 a = ((const float4*)src)[i];
    unsigned h0,l0,h1,l1;
    split2(a.x, a.y, h0, l0); split2(a.z, a.w, h1, l1);
    dh[2*i] = h0; dh[2*i + 1] = h1;
    dl[2*i] = l0; dl[2*i + 1] = l1;
}

// proj[b,i,h] = sum_s ss[b,i,s] * ssw[h,s]
__global__ void proj_kernel(const float* __restrict__ ss, const float* __restrict__ ssw){
    int gid = blockIdx.x * 256 + threadIdx.x;   // B*L*H = 65536
    int ih = gid >> 4;
    int h  = gid & 15;
    float acc = 0.f;
    #pragma unroll
    for (int s = 0; s < 8; s++) acc += ss[ih*8 + s] * ssw[h*8 + s];
    g_proj[gid] = acc;
}

// bias_base[b,i,j] = dist_pen + inter + struct  (head-independent part)
__global__ void bias_kernel(const float* __restrict__ pf, const int* __restrict__ aa,
                            const float* __restrict__ inter_mat,
                            const float* __restrict__ ps_p, const float* __restrict__ dd_p){
    __shared__ float s_inter[625];
    __shared__ float s_pi[16];
    int tid = threadIdx.x;
    int bi = blockIdx.x;            // b*L + i
    int b = bi >> 10, i = bi & 1023;
    for (int t = tid; t < 625; t += 256) s_inter[t] = inter_mat[t];
    if (tid < 16) s_pi[tid] = g_proj[bi*16 + tid];
    __syncthreads();

    float sigps = 1.f / (1.f + __expf(-ps_p[0]));
    float decay = fminf(fmaxf(dd_p[0], 0.1f), 5.0f);
    int ai = clampi(aa[bi], 0, 24);
    float pi[16];
    #pragma unroll
    for (int s = 0; s < 16; s++) pi[s] = s_pi[s];
    const float* projb = g_proj + (b << 10) * 16;
    int base = (b << 20) + (i << 10);

    for (int jj = 0; jj < 4; jj++){
        int j = tid + (jj << 8);
        float d = pf[base + j];
        d = fminf(fmaxf(d, 0.1f), 50.0f);
        float pen = -__powf(d, decay) * sigps;
        int aj = clampi(aa[(b << 10) + j], 0, 24);
        float sym = 0.5f * (s_inter[ai*25 + aj] + s_inter[aj*25 + ai]);
        float interv = sym / (1.0f + fabsf((float)(j - i)));
        const float* pj = projb + j*16;
        float dot = 0.f;
        #pragma unroll
        for (int s = 0; s < 16; s++) dot += pi[s] * pj[s];
        float st = 1.f / (1.f + __expf(-dot)) - 0.5f;
        g_bias[base + j] = pen + interv + st;
    }
}

// ---------------------------------------------------------------------------
// bf16x3 tensor GEMM from pre-packed operands. C = x @ W^T.
// z=0 -> Q packed, z=1 -> K packed, z=2 -> V fp32.
// ---------------------------------------------------------------------------
__global__ void __launch_bounds__(256,2) qkv_gemm_b3p(){
    __shared__ unsigned Ah[2][1152], Al[2][1152];   // 128 rows * 9 words
    __shared__ unsigned Bh[2][1152], Bl[2][1152];
    int z = blockIdx.z;
    const unsigned* Whp = g_wh + z*524288;
    const unsigned* Wlp = g_wl + z*524288;

    int tid = threadIdx.x;
    int warp = tid >> 5, lane = tid & 31;
    int g = lane >> 2, tg = lane & 3;
    int wm = warp >> 2, wn = warp & 3;
    int m0 = blockIdx.y << 7, n0 = blockIdx.x << 7;
    int row = tid >> 1, half = tid & 1;
    int wo = half << 2;

    float acc[4][4][4];
    #pragma unroll
    for (int a = 0; a < 4; a++)
        #pragma unroll
        for (int bq = 0; bq < 4; bq++)
            #pragma unroll
            for (int c = 0; c < 4; c++) acc[a][bq][c] = 0.f;

    // stage 0
    {
        uint4 ah4 = *(const uint4*)(g_xh + (m0 + row)*512 + wo);
        uint4 al4 = *(const uint4*)(g_xl + (m0 + row)*512 + wo);
        uint4 bh4 = *(const uint4*)(Whp + (n0 + row)*512 + wo);
        uint4 bl4 = *(const uint4*)(Wlp + (n0 + row)*512 + wo);
        int o = row*9 + wo;
        Ah[0][o] = ah4.x; Ah[0][o+1] = ah4.y; Ah[0][o+2] = ah4.z; Ah[0][o+3] = ah4.w;
        Al[0][o] = al4.x; Al[0][o+1] = al4.y; Al[0][o+2] = al4.z; Al[0][o+3] = al4.w;
        Bh[0][o] = bh4.x; Bh[0][o+1] = bh4.y; Bh[0][o+2] = bh4.z; Bh[0][o+3] = bh4.w;
        Bl[0][o] = bl4.x; Bl[0][o+1] = bl4.y; Bl[0][o+2] = bl4.z; Bl[0][o+3] = bl4.w;
    }
    __syncthreads();

    int s = 0;
    for (int kt = 0; kt < 64; kt++){
        uint4 pah, pal, pbh, pbl;
        if (kt < 63){
            int ko = ((kt + 1) << 3) + wo;
            pah = *(const uint4*)(g_xh + (m0 + row)*512 + ko);
            pal = *(const uint4*)(g_xl + (m0 + row)*512 + ko);
            pbh = *(const uint4*)(Whp + (n0 + row)*512 + ko);
            pbl = *(const uint4*)(Wlp + (n0 + row)*512 + ko);
        }

        unsigned bh[4][2], bl_[4][2];
        #pragma unroll
        for (int nt = 0; nt < 4; nt++){
            int nb = (wn << 5) + (nt << 3) + g;
            bh[nt][0]  = Bh[s][nb*9 + tg];     bh[nt][1]  = Bh[s][nb*9 + tg + 4];
            bl_[nt][0] = Bl[s][nb*9 + tg];     bl_[nt][1] = Bl[s][nb*9 + tg + 4];
        }
        #pragma unroll
        for (int mt = 0; mt < 4; mt++){
            int rb = (wm << 6) + (mt << 4);
            unsigned ah[4], al_[4];
            ah[0]  = Ah[s][(rb + g    )*9 + tg];     ah[1]  = Ah[s][(rb + g + 8)*9 + tg];
            ah[2]  = Ah[s][(rb + g    )*9 + tg + 4]; ah[3]  = Ah[s][(rb + g + 8)*9 + tg + 4];
            al_[0] = Al[s][(rb + g    )*9 + tg];     al_[1] = Al[s][(rb + g + 8)*9 + tg];
            al_[2] = Al[s][(rb + g    )*9 + tg + 4]; al_[3] = Al[s][(rb + g + 8)*9 + tg + 4];
            #pragma unroll
            for (int nt = 0; nt < 4; nt++){
                mma_bf16(acc[mt][nt], ah,  bh[nt]);
                mma_bf16(acc[mt][nt], ah,  bl_[nt]);
                mma_bf16(acc[mt][nt], al_, bh[nt]);
            }
        }

        if (kt < 63){
            int o = row*9 + wo;
            Ah[s^1][o] = pah.x; Ah[s^1][o+1] = pah.y; Ah[s^1][o+2] = pah.z; Ah[s^1][o+3] = pah.w;
            Al[s^1][o] = pal.x; Al[s^1][o+1] = pal.y; Al[s^1][o+2] = pal.z; Al[s^1][o+3] = pal.w;
            Bh[s^1][o] = pbh.x; Bh[s^1][o+1] = pbh.y; Bh[s^1][o+2] = pbh.z; Bh[s^1][o+3] = pbh.w;
            Bl[s^1][o] = pbl.x; Bl[s^1][o+1] = pbl.y; Bl[s^1][o+2] = pbl.z; Bl[s^1][o+3] = pbl.w;
        }
        __syncthreads();
        s ^= 1;
    }

    // epilogue (head stride = 32768 packed words -> shift 15)
    unsigned* oh = (z == 0) ? g_qh : g_kh;
    unsigned* ol = (z == 0) ? g_ql : g_kl;
    #pragma unroll
    for (int mt = 0; mt < 4; mt++){
        #pragma unroll
        for (int nt = 0; nt < 4; nt++){
            int m = m0 + (wm << 6) + (mt << 4) + g;
            int n = n0 + (wn << 5) + (nt << 3) + (tg << 1);
            int b = m >> 10, li = m & 1023;
            int h = n >> 6, dd = n & 63;
            if (z == 2){
                float* p0 = g_v + ((((b << 4) + h) << 16) + (li << 6) + dd);
                *(float2*)p0 = make_float2(acc[mt][nt][0], acc[mt][nt][1]);
                float* p1 = g_v + ((((b << 4) + h) << 16) + ((li + 8) << 6) + dd);
                *(float2*)p1 = make_float2(acc[mt][nt][2], acc[mt][nt][3]);
            } else {
                int cb = (((b << 4) + h) << 15) + (dd >> 1);
                unsigned hw, lw;
                split2(acc[mt][nt][0], acc[mt][nt][1], hw, lw);
                oh[cb + (li << 5)] = hw; ol[cb + (li << 5)] = lw;
                split2(acc[mt][nt][2], acc[mt][nt][3], hw, lw);
                oh[cb + ((li + 8) << 5)] = hw; ol[cb + ((li + 8) << 5)] = lw;
            }
        }
    }
}

// out = ctx @ Wo^T + bo, ctx pre-packed hi/lo, Wo pre-packed.
__global__ void __launch_bounds__(256,2) out_gemm_b3p(const float* __restrict__ bo,
                                                      float* __restrict__ outp){
    __shared__ unsigned Ah[2][1152], Al[2][1152];
    __shared__ unsigned Bh[2][1152], Bl[2][1152];
    const unsigned* Whp = g_wh + 3*524288;
    const unsigned* Wlp = g_wl + 3*524288;
    int tid = threadIdx.x;
    int warp = tid >> 5, lane = tid & 31;
    int g = lane >> 2, tg = lane & 3;
    int wm = warp >> 2, wn = warp & 3;
    int m0 = blockIdx.y << 7, n0 = blockIdx.x << 7;
    int row = tid >> 1, half = tid & 1;
    int wo = half << 2;
    int m = m0 + row, b = m >> 10, li = m & 1023;

    float acc[4][4][4];
    #pragma unroll
    for (int a = 0; a < 4; a++)
        #pragma unroll
        for (int bq = 0; bq < 4; bq++)
            #pragma unroll
            for (int c = 0; c < 4; c++) acc[a][bq][c] = 0.f;

    {
        int cw = (((b << 4) + 0) << 15) + (li << 5) + wo;   // kt=0 -> h=0, d-word 0
        uint4 ah4 = *(const uint4*)(g_ctxh + cw);
        uint4 al4 = *(const uint4*)(g_ctxl + cw);
        uint4 bh4 = *(const uint4*)(Whp + (n0 + row)*512 + wo);
        uint4 bl4 = *(const uint4*)(Wlp + (n0 + row)*512 + wo);
        int o = row*9 + wo;
        Ah[0][o] = ah4.x; Ah[0][o+1] = ah4.y; Ah[0][o+2] = ah4.z; Ah[0][o+3] = ah4.w;
        Al[0][o] = al4.x; Al[0][o+1] = al4.y; Al[0][o+2] = al4.z; Al[0][o+3] = al4.w;
        Bh[0][o] = bh4.x; Bh[0][o+1] = bh4.y; Bh[0][o+2] = bh4.z; Bh[0][o+3] = bh4.w;
        Bl[0][o] = bl4.x; Bl[0][o+1] = bl4.y; Bl[0][o+2] = bl4.z; Bl[0][o+3] = bl4.w;
    }
    __syncthreads();

    int s = 0;
    for (int kt = 0; kt < 64; kt++){
        uint4 pah, pal, pbh, pbl;
        if (kt < 63){
            int k0 = (kt + 1) << 4;
            int hh = k0 >> 6, dw = ((k0 & 63) >> 1) + wo;
            int cw = (((b << 4) + hh) << 15) + (li << 5) + dw;
            pah = *(const uint4*)(g_ctxh + cw);
            pal = *(const uint4*)(g_ctxl + cw);
            int ko = ((kt + 1) << 3) + wo;
            pbh = *(const uint4*)(Whp + (n0 + row)*512 + ko);
            pbl = *(const uint4*)(Wlp + (n0 + row)*512 + ko);
        }

        unsigned bh[4][2], bl_[4][2];
        #pragma unroll
        for (int nt = 0; nt < 4; nt++){
            int nb = (wn << 5) + (nt << 3) + g;
            bh[nt][0]  = Bh[s][nb*9 + tg];     bh[nt][1]  = Bh[s][nb*9 + tg + 4];
            bl_[nt][0] = Bl[s][nb*9 + tg];     bl_[nt][1] = Bl[s][nb*9 + tg + 4];
        }
        #pragma unroll
        for (int mt = 0; mt < 4; mt++){
            int rb = (wm << 6) + (mt << 4);
            unsigned ah[4], al_[4];
            ah[0]  = Ah[s][(rb + g    )*9 + tg];     ah[1]  = Ah[s][(rb + g + 8)*9 + tg];
            ah[2]  = Ah[s][(rb + g    )*9 + tg + 4]; ah[3]  = Ah[s][(rb + g + 8)*9 + tg + 4];
            al_[0] = Al[s][(rb + g    )*9 + tg];     al_[1] = Al[s][(rb + g + 8)*9 + tg];
            al_[2] = Al[s][(rb + g    )*9 + tg + 4]; al_[3] = Al[s][(rb + g + 8)*9 + tg + 4];
            #pragma unroll
            for (int nt = 0; nt < 4; nt++){
                mma_bf16(acc[mt][nt], ah,  bh[nt]);
                mma_bf16(acc[mt][nt], ah,  bl_[nt]);
                mma_bf16(acc[mt][nt], al_, bh[nt]);
            }
        }

        if (kt < 63){
            int o = row*9 + wo;
            Ah[s^1][o] = pah.x; Ah[s^1][o+1] = pah.y; Ah[s^1][o+2] = pah.z; Ah[s^1][o+3] = pah.w;
            Al[s^1][o] = pal.x; Al[s^1][o+1] = pal.y; Al[s^1][o+2] = pal.z; Al[s^1][o+3] = pal.w;
            Bh[s^1][o] = pbh.x; Bh[s^1][o+1] = pbh.y; Bh[s^1][o+2] = pbh.z; Bh[s^1][o+3] = pbh.w;
            Bl[s^1][o] = pbl.x; Bl[s^1][o+1] = pbl.y; Bl[s^1][o+2] = pbl.z; Bl[s^1][o+3] = pbl.w;
        }
        __syncthreads();
        s ^= 1;
    }

    #pragma unroll
    for (int mt = 0; mt < 4; mt++){
        #pragma unroll
        for (int nt = 0; nt < 4; nt++){
            int mm = m0 + (wm << 6) + (mt << 4) + g;
            int n = n0 + (wn << 5) + (nt << 3) + (tg << 1);
            float b0v = bo[n], b1v = bo[n + 1];
            *(float2*)(outp + mm*1024 + n) = make_float2(acc[mt][nt][0] + b0v, acc[mt][nt][1] + b1v);
            *(float2*)(outp + (mm + 8)*1024 + n) = make_float2(acc[mt][nt][2] + b0v, acc[mt][nt][3] + b1v);
        }
    }
}

// ---------------------------------------------------------------------------
// MMA flash attention (bf16x3): Q/K pre-packed; V fp32 split along j in-kernel.
// ---------------------------------------------------------------------------
#define AQS 36
#define AVS 68
#define SM_QH 0
#define SM_QL (128*AQS)
#define SM_KH (2*128*AQS)
#define SM_KL (3*128*AQS)
#define SM_VH (4*128*AQS)
#define SM_VL (4*128*AQS + 64*AVS)
#define ATTN_SMEM ((4*128*AQS + 2*64*AVS) * 4)

__global__ void __launch_bounds__(256,1) attn_mma(const float* __restrict__ dist_bias){
    extern __shared__ unsigned smw[];
    int b = blockIdx.z, h = blockIdx.y, it = blockIdx.x;
    int i0 = it << 7;
    int tid = threadIdx.x;
    int warp = tid >> 5, lane = tid & 31;
    int g = lane >> 2, tg = lane & 3;
    int rb = warp << 4;
    int hb = (((b << 4) + h) << 15);   // head stride = 32768 packed words
    const float* vb = g_v + (((b << 4) + h) << 16);
    const float* biasb = g_bias + (b << 20);
    float db = dist_bias[h];

    // stage Q (packed copy)
    #pragma unroll
    for (int l = 0; l < 4; l++){
        int id = tid + (l << 8);
        int rw = id >> 3, q = id & 7;
        int gw = hb + ((i0 + rw) << 5) + (q << 2);
        uint4 hw = *(const uint4*)(g_qh + gw);
        uint4 lw = *(const uint4*)(g_ql + gw);
        int o = rw*AQS + (q << 2);
        *(uint4*)&smw[SM_QH + o] = hw;
        *(uint4*)&smw[SM_QL + o] = lw;
    }

    float m0 = -INFINITY, m1 = -INFINITY, l0s = 0.f, l1s = 0.f;
    float cacc[8][4];
    #pragma unroll
    for (int dt = 0; dt < 8; dt++)
        #pragma unroll
        for (int c = 0; c < 4; c++) cacc[dt][c] = 0.f;

    for (int jt = 0; jt < 8; jt++){
        int j0 = jt << 7;
        __syncthreads();
        // stage K (packed copy)
        #pragma unroll
        for (int l = 0; l < 4; l++){
            int id = tid + (l << 8);
            int rw = id >> 3, q = id & 7;
            int gw = hb + ((j0 + rw) << 5) + (q << 2);
            uint4 hw = *(const uint4*)(g_kh + gw);
            uint4 lw = *(const uint4*)(g_kl + gw);
            int o = rw*AQS + (q << 2);
            *(uint4*)&smw[SM_KH + o] = hw;
            *(uint4*)&smw[SM_KL + o] = lw;
        }
        // stage V j-pair packed: word = (v[2jp][d], v[2jp+1][d])
        #pragma unroll
        for (int l = 0; l < 4; l++){
            int id = tid + (l << 8);
            int jp = id >> 4, dq = (id & 15) << 2;
            float4 va = *(const float4*)(vb + ((j0 + (jp << 1)) << 6) + dq);
            float4 vc = *(const float4*)(vb + ((j0 + (jp << 1) + 1) << 6) + dq);
            unsigned hw, lw;
            int o = jp*AVS + dq;
            split2(va.x, vc.x, hw, lw); smw[SM_VH + o    ] = hw; smw[SM_VL + o    ] = lw;
            split2(va.y, vc.y, hw, lw); smw[SM_VH + o + 1] = hw; smw[SM_VL + o + 1] = lw;
            split2(va.z, vc.z, hw, lw); smw[SM_VH + o + 2] = hw; smw[SM_VL + o + 2] = lw;
            split2(va.w, vc.w, hw, lw); smw[SM_VH + o + 3] = hw; smw[SM_VL + o + 3] = lw;
        }
        __syncthreads();

        // S = Q K^T : warp computes m16 x n128, k=64
        float sacc[16][4];
        #pragma unroll
        for (int nt = 0; nt < 16; nt++)
            #pragma unroll
            for (int c = 0; c < 4; c++) sacc[nt][c] = 0.f;

        #pragma unroll
        for (int ks = 0; ks < 4; ks++){
            unsigned ah[4], al_[4];
            int ro = (rb + g)*AQS + (ks << 3);
            int r1 = ro + 8*AQS;
            ah[0]  = smw[SM_QH + ro + tg];     ah[1]  = smw[SM_QH + r1 + tg];
            ah[2]  = smw[SM_QH + ro + 4 + tg]; ah[3]  = smw[SM_QH + r1 + 4 + tg];
            al_[0] = smw[SM_QL + ro + tg];     al_[1] = smw[SM_QL + r1 + tg];
            al_[2] = smw[SM_QL + ro + 4 + tg]; al_[3] = smw[SM_QL + r1 + 4 + tg];
            #pragma unroll
            for (int nt = 0; nt < 16; nt++){
                int ko = ((nt << 3) + g)*AQS + (ks << 3);
                unsigned bh[2], bl_[2];
                bh[0]  = smw[SM_KH + ko + tg]; bh[1]  = smw[SM_KH + ko + 4 + tg];
                bl_[0] = smw[SM_KL + ko + tg]; bl_[1] = smw[SM_KL + ko + 4 + tg];
                mma_bf16(sacc[nt], ah,  bh);
                mma_bf16(sacc[nt], ah,  bl_);
                mma_bf16(sacc[nt], al_, bh);
            }
        }

        // scale + bias
        int row0 = i0 + rb + g;
        const float* bp0 = biasb + (row0 << 10) + j0;
        const float* bp1 = biasb + ((row0 + 8) << 10) + j0;
        #pragma unroll
        for (int nt = 0; nt < 16; nt++){
            int col = (nt << 3) + (tg << 1);
            float2 b0 = *(const float2*)(bp0 + col);
            float2 b1 = *(const float2*)(bp1 + col);
            sacc[nt][0] = sacc[nt][0]*0.125f + b0.x + db;
            sacc[nt][1] = sacc[nt][1]*0.125f + b0.y + db;
            sacc[nt][2] = sacc[nt][2]*0.125f + b1.x + db;
            sacc[nt][3] = sacc[nt][3]*0.125f + b1.y + db;
        }

        // online softmax (quad reduce)
        float mx0 = -INFINITY, mx1 = -INFINITY;
        #pragma unroll
        for (int nt = 0; nt < 16; nt++){
            mx0 = fmaxf(mx0, fmaxf(sacc[nt][0], sacc[nt][1]));
            mx1 = fmaxf(mx1, fmaxf(sacc[nt][2], sacc[nt][3]));
        }
        mx0 = fmaxf(mx0, __shfl_xor_sync(0xffffffffu, mx0, 1));
        mx0 = fmaxf(mx0, __shfl_xor_sync(0xffffffffu, mx0, 2));
        mx1 = fmaxf(mx1, __shfl_xor_sync(0xffffffffu, mx1, 1));
        mx1 = fmaxf(mx1, __shfl_xor_sync(0xffffffffu, mx1, 2));

        float mn0 = fmaxf(m0, mx0), mn1 = fmaxf(m1, mx1);
        float cr0 = __expf(m0 - mn0), cr1 = __expf(m1 - mn1);
        float sum0 = 0.f, sum1 = 0.f;
        #pragma unroll
        for (int nt = 0; nt < 16; nt++){
            sacc[nt][0] = __expf(sacc[nt][0] - mn0);
            sacc[nt][1] = __expf(sacc[nt][1] - mn0);
            sacc[nt][2] = __expf(sacc[nt][2] - mn1);
            sacc[nt][3] = __expf(sacc[nt][3] - mn1);
            sum0 += sacc[nt][0] + sacc[nt][1];
            sum1 += sacc[nt][2] + sacc[nt][3];
        }
        sum0 += __shfl_xor_sync(0xffffffffu, sum0, 1);
        sum0 += __shfl_xor_sync(0xffffffffu, sum0, 2);
        sum1 += __shfl_xor_sync(0xffffffffu, sum1, 1);
        sum1 += __shfl_xor_sync(0xffffffffu, sum1, 2);
        l0s = l0s*cr0 + sum0;  m0 = mn0;
        l1s = l1s*cr1 + sum1;  m1 = mn1;
        #pragma unroll
        for (int dt = 0; dt < 8; dt++){
            cacc[dt][0] *= cr0; cacc[dt][1] *= cr0;
            cacc[dt][2] *= cr1; cacc[dt][3] *= cr1;
        }

        // ctx += P V : P from sacc (C-frag == A-frag)
        #pragma unroll
        for (int jb = 0; jb < 8; jb++){
            unsigned aph[4], apl[4];
            split2(sacc[2*jb  ][0], sacc[2*jb  ][1], aph[0], apl[0]);
            split2(sacc[2*jb  ][2], sacc[2*jb  ][3], aph[1], apl[1]);
            split2(sacc[2*jb+1][0], sacc[2*jb+1][1], aph[2], apl[2]);
            split2(sacc[2*jb+1][2], sacc[2*jb+1][3], aph[3], apl[3]);
            #pragma unroll
            for (int dt = 0; dt < 8; dt++){
                int v0 = ((jb << 3) + tg)*AVS + (dt << 3) + g;
                int v1 = ((jb << 3) + 4 + tg)*AVS + (dt << 3) + g;
                unsigned bh[2], bl_[2];
                bh[0]  = smw[SM_VH + v0]; bh[1]  = smw[SM_VH + v1];
                bl_[0] = smw[SM_VL + v0]; bl_[1] = smw[SM_VL + v1];
                mma_bf16(cacc[dt], aph, bh);
                mma_bf16(cacc[dt], aph, bl_);
                mma_bf16(cacc[dt], apl, bh);
            }
        }
    }

    // write ctx packed hi/lo (pairs along d)
    float inv0 = 1.f / l0s, inv1 = 1.f / l1s;
    int row0 = i0 + rb + g;
    #pragma unroll
    for (int dt = 0; dt < 8; dt++){
        int dw = ((dt << 3) + (tg << 1)) >> 1;
        unsigned hw, lw;
        int idx0 = hb + (row0 << 5) + dw;
        split2(cacc[dt][0]*inv0, cacc[dt][1]*inv0, hw, lw);
        g_ctxh[idx0] = hw; g_ctxl[idx0] = lw;
        int idx1 = hb + ((row0 + 8) << 5) + dw;
        split2(cacc[dt][2]*inv1, cacc[dt][3]*inv1, hw, lw);
        g_ctxh[idx1] = hw; g_ctxl[idx1] = lw;
    }
}

extern "C" void kernel_launch(void* const* d_in, const int* in_sizes, int n_in,
                              void* d_out, int out_size){
    const float* x         = (const float*)d_in[0];
    const float* pf        = (const float*)d_in[1];
    const int*   aa        = (const int*)  d_in[2];
    const float* ss        = (const float*)d_in[3];
    const float* Wq        = (const float*)d_in[4];
    const float* Wk        = (const float*)d_in[5];
    const float* Wv        = (const float*)d_in[6];
    const float* Wo        = (const float*)d_in[7];
    const float* bo        = (const float*)d_in[8];
    const float* dist_bias = (const float*)d_in[9];
    const float* inter_mat = (const float*)d_in[10];
    const float* ssw       = (const float*)d_in[11];
    const float* ps        = (const float*)d_in[12];
    const float* dd        = (const float*)d_in[13];
    float* out = (float*)d_out;

    unsigned *xh, *xl, *wh, *wl;
    cudaGetSymbolAddress((void**)&xh, g_xh);
    cudaGetSymbolAddress((void**)&xl, g_xl);
    cudaGetSymbolAddress((void**)&wh, g_wh);
    cudaGetSymbolAddress((void**)&wl, g_wl);

    prep_convert<<<4096, 256>>>(x, xh, xl, 1048576);
    prep_convert<<<1024, 256>>>(Wq, wh,            wl,            262144);
    prep_convert<<<1024, 256>>>(Wk, wh + 524288,   wl + 524288,   262144);
    prep_convert<<<1024, 256>>>(Wv, wh + 1048576,  wl + 1048576,  262144);
    prep_convert<<<1024, 256>>>(Wo, wh + 1572864,  wl + 1572864,  262144);

    proj_kernel<<<256, 256>>>(ss, ssw);
    bias_kernel<<<4096, 256>>>(pf, aa, inter_mat, ps, dd);

    dim3 gq(8, 32, 3);
    qkv_gemm_b3p<<<gq, 256>>>();

    cudaFuncSetAttribute(attn_mma, cudaFuncAttributeMaxDynamicSharedMemorySize, ATTN_SMEM);
    dim3 ga(8, 16, 4);
    attn_mma<<<ga, 256, ATTN_SMEM>>>(dist_bias);

    dim3 go(8, 32, 1);
    out_gemm_b3p<<<go, 256>>>(bo, out);
}